// round 7
// baseline (speedup 1.0000x reference)
#include <cuda_runtime.h>
#include <cstdint>

// Fixed-shape problem: H=480, W=640, N=1e6
#define HH 480
#define WW 640
#define HW (HH * WW)

typedef unsigned long long u64;

#define SMASK 0x8000000080000000ULL
#define AMASK 0x7fffffff7fffffffULL

// last-write-wins scatter scratch: (n+1)<<32 | float_bits(kp).
// Zero-initialized at module load; finalize_depth_kernel resets it to zero
// after every use, so every kernel_launch call sees a zeroed array.
__device__ u64 g_scratch[HW];

__global__ void finalize_depth_kernel(float* __restrict__ out) {
    int i = blockIdx.x * blockDim.x + threadIdx.x;
    if (i < HW) {
        u64 p = g_scratch[i];
        out[i] = __uint_as_float((unsigned)(p & 0xffffffffULL));
        g_scratch[i] = 0ULL;  // leave zeroed for the next launch/replay
    }
}

// ---- packed f32x2 helpers (1 SASS instr = 2 points' flop) ----
__device__ __forceinline__ u64 pk2(float lo, float hi) {
    u64 r;
    asm("mov.b64 %0, {%1, %2};" : "=l"(r)
        : "r"(__float_as_uint(lo)), "r"(__float_as_uint(hi)));
    return r;
}
__device__ __forceinline__ void unpk2(u64 v, float& lo, float& hi) {
    unsigned a, b;
    asm("mov.b64 {%0, %1}, %2;" : "=r"(a), "=r"(b) : "l"(v));
    lo = __uint_as_float(a);
    hi = __uint_as_float(b);
}
__device__ __forceinline__ u64 f2fma(u64 a, u64 b, u64 c) {
    u64 d;
    asm("fma.rn.f32x2 %0, %1, %2, %3;" : "=l"(d) : "l"(a), "l"(b), "l"(c));
    return d;
}
__device__ __forceinline__ u64 f2mul(u64 a, u64 b) {
    u64 d;
    asm("mul.rn.f32x2 %0, %1, %2;" : "=l"(d) : "l"(a), "l"(b));
    return d;
}
__device__ __forceinline__ u64 f2add(u64 a, u64 b) {
    u64 d;
    asm("add.rn.f32x2 %0, %1, %2;" : "=l"(d) : "l"(a), "l"(b));
    return d;
}

// Packed bit-trick rsqrt, TWO Newton steps (~1e-6 rel err). One step was not
// enough: the rotation ANGLE tan(t)=S/w does not fully cancel the rsq error
// (it cancels in S/cos2 but not through w=(1+cos2)/2), and Jacobi's floor is
// set by per-rotation accuracy (round-6 lesson: 1-NR -> rel_err 3.5e-3).
// Both halves must be > 0. AMASK strips the bit crossing the lane boundary.
__device__ __forceinline__ u64 f2rsqrt2(u64 x, u64 MHALF, u64 C15) {
    u64 y = 0x5f375a865f375a86ULL - ((x >> 1) & AMASK);
    u64 xnh = f2mul(MHALF, x);            // -0.5*x
    u64 yy = f2mul(y, y);
    y = f2mul(y, f2fma(xnh, yy, C15));    // NR step 1
    yy = f2mul(y, y);
    y = f2mul(y, f2fma(xnh, yy, C15));    // NR step 2
    return y;
}

__global__ void __launch_bounds__(256) triangulate_kernel(
    const float* __restrict__ T,      // [4,4]
    const float* __restrict__ K0,     // [3,3]
    const float* __restrict__ K1,     // [3,3]
    const float* __restrict__ mconf,  // [N]
    const float* __restrict__ kpts0,  // [N,2]
    const float* __restrict__ kpts1,  // [N,2]
    float* __restrict__ out,          // [HW + N]
    int n)
{
    int t = blockIdx.x * blockDim.x + threadIdx.x;
    int i0 = 2 * t;
    if (i0 >= n) return;
    bool two = (i0 + 1 < n);

    // ---- camera constants (broadcast loads, L1-resident) ----
    float fx0 = __ldg(K0 + 0), cx0 = __ldg(K0 + 2);
    float fy0 = __ldg(K0 + 4), cy0 = __ldg(K0 + 5);

    // P1 = K1 @ T[:3,:]  (3x4)
    float p1[3][4];
#pragma unroll
    for (int r = 0; r < 3; r++) {
        float k0c = __ldg(K1 + r * 3 + 0);
        float k1c = __ldg(K1 + r * 3 + 1);
        float k2c = __ldg(K1 + r * 3 + 2);
#pragma unroll
        for (int c = 0; c < 4; c++) {
            p1[r][c] = k0c * __ldg(T + 0 * 4 + c)
                     + k1c * __ldg(T + 1 * 4 + c)
                     + k2c * __ldg(T + 2 * 4 + c);
        }
    }

    // ---- per-pair data (vector loads: float4 = two points' x,y) ----
    float x0a, y0a, x1a, y1a, ma, x0b, y0b, x1b, y1b, mb;
    if (two) {
        float4 q0 = __ldg(((const float4*)kpts0) + t);
        float4 q1 = __ldg(((const float4*)kpts1) + t);
        float2 mm = __ldg(((const float2*)mconf) + t);
        x0a = q0.x; y0a = q0.y; x0b = q0.z; y0b = q0.w;
        x1a = q1.x; y1a = q1.y; x1b = q1.z; y1b = q1.w;
        ma = mm.x;  mb = mm.y;
    } else {
        float2 q0 = __ldg(((const float2*)kpts0) + i0);
        float2 q1 = __ldg(((const float2*)kpts1) + i0);
        ma = __ldg(mconf + i0);
        x0a = q0.x; y0a = q0.y; x1a = q1.x; y1a = q1.y;
        x0b = x0a; y0b = y0a; x1b = x1a; y1b = y1a; mb = ma;  // duplicate lane
    }

    // ---- build A rows 2,3 per point (rows 0,1 are the sparse K0 rows) ----
    float r2a[4], r3a[4], r2b[4], r3b[4];
#pragma unroll
    for (int j = 0; j < 4; j++) {
        r2a[j] = ma * fmaf(x1a, p1[2][j], -p1[0][j]);
        r3a[j] = ma * fmaf(y1a, p1[2][j], -p1[1][j]);
        r2b[j] = mb * fmaf(x1b, p1[2][j], -p1[0][j]);
        r3b[j] = mb * fmaf(y1b, p1[2][j], -p1[1][j]);
    }

    // ---- pack A as 4 columns x 4 rows of f32x2 (lo=point a, hi=point b) ----
    u64 a[4][4];
    u64 nfx = pk2(-fx0, -fx0), nfy = pk2(-fy0, -fy0);
    a[0][0] = nfx;  a[0][1] = 0ULL;
    a[0][2] = pk2(r2a[0], r2b[0]);  a[0][3] = pk2(r3a[0], r3b[0]);
    a[1][0] = 0ULL; a[1][1] = nfy;
    a[1][2] = pk2(r2a[1], r2b[1]);  a[1][3] = pk2(r3a[1], r3b[1]);
    a[2][0] = pk2(x0a - cx0, x0b - cx0);
    a[2][1] = pk2(y0a - cy0, y0b - cy0);
    a[2][2] = pk2(r2a[2], r2b[2]);  a[2][3] = pk2(r3a[2], r3b[2]);
    a[3][0] = 0ULL; a[3][1] = 0ULL;
    a[3][2] = pk2(r2a[3], r2b[3]);  a[3][3] = pk2(r3a[3], r3b[3]);

    const u64 ONE   = 0x3F8000003F800000ULL;
    const u64 NEG1  = 0xBF800000BF800000ULL;
    const u64 HALFC = 0x3F0000003F000000ULL;
    const u64 MHALF = 0xBF000000BF000000ULL;
    const u64 C15   = 0x3FC000003FC00000ULL;
    const u64 TINY  = 0x0F8000000F800000ULL;  // 2^-96 per half: keeps u > 0

    // Track only rows 2,3 of V (all the answer needs)
    u64 v2[4] = {0ULL, 0ULL, ONE, 0ULL};
    u64 v3[4] = {0ULL, 0ULL, 0ULL, ONE};

    const int PP[6] = {0, 0, 0, 1, 1, 2};
    const int QQ[6] = {1, 2, 3, 2, 3, 3};

    // ---- one-sided Jacobi SVD, 5 cyclic sweeps, fully packed ----
#pragma unroll
    for (int sweep = 0; sweep < 5; sweep++) {
#pragma unroll
        for (int rr = 0; rr < 6; rr++) {
            const int p = PP[rr], q = QQ[rr];
            // Gram entries of the column pair
            u64 al = f2mul(a[p][0], a[p][0]);
            u64 be = f2mul(a[q][0], a[q][0]);
            u64 g  = f2mul(a[p][0], a[q][0]);
#pragma unroll
            for (int k = 1; k < 4; k++) {
                al = f2fma(a[p][k], a[p][k], al);
                be = f2fma(a[q][k], a[q][k], be);
                g  = f2fma(a[p][k], a[q][k], g);
            }
            u64 d  = f2fma(al, NEG1, be);              // be - al
            u64 tg = f2add(g, g);
            u64 u_ = f2fma(tg, tg, f2fma(d, d, TINY)); // d^2 + 4g^2 (+floor)
            u64 rsq = f2rsqrt2(u_, MHALF, C15);
            u64 cos2 = f2mul(d & AMASK, rsq);          // |d|/sqrt(u) = cos(2t)
            u64 w  = f2fma(HALFC, cos2, HALFC);        // (1+cos2)/2 = cos(t)^2
            u64 S  = f2mul(g, rsq) ^ (d & SMASK);      // sign(d)*g/sqrt(u) = sin2/2
            u64 rw = f2rsqrt2(w, MHALF, C15);
            u64 c  = f2mul(w, rw);                     // cos(t)
            u64 s  = f2mul(S, rw);                     // sin(t)
            u64 sn = s ^ SMASK;
            // rotate columns p,q of A
#pragma unroll
            for (int k = 0; k < 4; k++) {
                u64 ap = a[p][k], aq = a[q][k];
                a[p][k] = f2fma(sn, aq, f2mul(c, ap));
                a[q][k] = f2fma(s,  ap, f2mul(c, aq));
            }
            // rotate tracked V rows
            {
                u64 t2p = v2[p], t2q = v2[q];
                v2[p] = f2fma(sn, t2q, f2mul(c, t2p));
                v2[q] = f2fma(s,  t2p, f2mul(c, t2q));
                u64 t3p = v3[p], t3q = v3[q];
                v3[p] = f2fma(sn, t3q, f2mul(c, t3p));
                v3[q] = f2fma(s,  t3p, f2mul(c, t3q));
            }
        }
    }

    // ---- column norms (= singular values, rotations are orthonormal) ----
    float nA[4], nB[4], v2A[4], v2B[4], v3A[4], v3B[4];
#pragma unroll
    for (int j = 0; j < 4; j++) {
        u64 n2 = f2mul(a[j][0], a[j][0]);
#pragma unroll
        for (int k = 1; k < 4; k++) n2 = f2fma(a[j][k], a[j][k], n2);
        unpk2(n2, nA[j], nB[j]);
        unpk2(v2[j], v2A[j], v2B[j]);
        unpk2(v3[j], v3A[j], v3B[j]);
    }

    // ---- per-point finish: argmin column, depth, clips, scatter ----
    float kpA, kpB = 0.0f;
    {
        int jm = 0; float best = nA[0];
#pragma unroll
        for (int j = 1; j < 4; j++) if (nA[j] < best) { best = nA[j]; jm = j; }
        float z = __fdividef(v2A[jm], v3A[jm]);
        z = fminf(fmaxf(z, -1000.0f), 1000.0f);
        float z2 = fminf(fmaxf(z, 0.0f), 30.0f);
        kpA = (z2 > 0.0f && z2 < 30.0f) ? z2 : 0.0f;
        u64 packed = (((u64)(unsigned)(i0 + 1)) << 32) | (u64)__float_as_uint(kpA);
        atomicMax(&g_scratch[(int)y0a * WW + (int)x0a], packed);
    }
    if (two) {
        int jm = 0; float best = nB[0];
#pragma unroll
        for (int j = 1; j < 4; j++) if (nB[j] < best) { best = nB[j]; jm = j; }
        float z = __fdividef(v2B[jm], v3B[jm]);
        z = fminf(fmaxf(z, -1000.0f), 1000.0f);
        float z2 = fminf(fmaxf(z, 0.0f), 30.0f);
        kpB = (z2 > 0.0f && z2 < 30.0f) ? z2 : 0.0f;
        u64 packed = (((u64)(unsigned)(i0 + 2)) << 32) | (u64)__float_as_uint(kpB);
        atomicMax(&g_scratch[(int)y0b * WW + (int)x0b], packed);
        *(float2*)(out + HW + i0) = make_float2(kpA, kpB);
    } else {
        out[HW + i0] = kpA;
    }
}

extern "C" void kernel_launch(void* const* d_in, const int* in_sizes, int n_in,
                              void* d_out, int out_size) {
    // metadata order: T_0to1, K0, K1, mconf, mkpts0_f, mkpts1_f, image0, m_bids
    const float* T     = (const float*)d_in[0];
    const float* K0    = (const float*)d_in[1];
    const float* K1    = (const float*)d_in[2];
    const float* mconf = (const float*)d_in[3];
    const float* kp0   = (const float*)d_in[4];
    const float* kp1   = (const float*)d_in[5];
    float* out = (float*)d_out;
    int n = in_sizes[3];  // mconf element count = N

    const int T1 = 256;
    int nthreads = (n + 1) / 2;
    triangulate_kernel<<<(nthreads + T1 - 1) / T1, T1>>>(T, K0, K1, mconf, kp0, kp1, out, n);
    finalize_depth_kernel<<<(HW + T1 - 1) / T1, T1>>>(out);
}

// round 10
// speedup vs baseline: 1.1887x; 1.1887x over previous
#include <cuda_runtime.h>
#include <cstdint>

// Fixed-shape problem: H=480, W=640, N=1e6
#define HH 480
#define WW 640
#define HW (HH * WW)

typedef unsigned long long u64;

// last-write-wins scatter scratch: (n+1)<<32 | float_bits(kp).
// Zero-initialized at module load; finalize_depth_kernel resets it to zero
// after every use, so every kernel_launch call (and graph replay) sees zeros.
__device__ u64 g_scratch[HW];

// Precomputed camera constants: [0..11] = P1 = K1 @ T[:3,:] (row-major 3x4),
// [12..15] = fx0, cx0, fy0, cy0.
__device__ __align__(16) float g_pre[16];

__global__ void setup_kernel(const float* __restrict__ T,
                             const float* __restrict__ K0,
                             const float* __restrict__ K1) {
    if (threadIdx.x == 0 && blockIdx.x == 0) {
#pragma unroll
        for (int r = 0; r < 3; r++)
#pragma unroll
            for (int c = 0; c < 4; c++)
                g_pre[r * 4 + c] = K1[r * 3 + 0] * T[0 * 4 + c]
                                 + K1[r * 3 + 1] * T[1 * 4 + c]
                                 + K1[r * 3 + 2] * T[2 * 4 + c];
        g_pre[12] = K0[0];  // fx0
        g_pre[13] = K0[2];  // cx0
        g_pre[14] = K0[4];  // fy0
        g_pre[15] = K0[5];  // cy0
    }
}

__global__ void finalize_depth_kernel(float* __restrict__ out) {
    int i = blockIdx.x * blockDim.x + threadIdx.x;
    if (i < HW) {
        u64 p = g_scratch[i];
        out[i] = __uint_as_float((unsigned)(p & 0xffffffffULL));
        g_scratch[i] = 0ULL;  // leave zeroed for the next replay
    }
}

// Bit-trick rsqrt + 2 Newton steps: pure FMA/ALU (keeps off the quarter-rate
// MUFU pipe). ~1e-6 rel err; proven accuracy floor (round 4: 1.48e-5).
__device__ __forceinline__ float frsqrt(float x) {
    float y = __uint_as_float(0x5f375a86u - (__float_as_uint(x) >> 1));
    float xh = 0.5f * x;
    y = y * (1.5f - xh * y * y);
    y = y * (1.5f - xh * y * y);
    return y;
}

__global__ void __launch_bounds__(256) triangulate_kernel(
    const float* __restrict__ mconf,  // [N]
    const float* __restrict__ kpts0,  // [N,2]
    const float* __restrict__ kpts1,  // [N,2]
    float* __restrict__ out,          // [HW + N]
    int n)
{
    int i = blockIdx.x * blockDim.x + threadIdx.x;
    if (i >= n) return;

    // ---- precomputed constants (4x float4 broadcast loads) ----
    const float4* pre4 = (const float4*)g_pre;
    float4 P0  = __ldg(pre4 + 0);  // P1 row 0
    float4 P1r = __ldg(pre4 + 1);  // P1 row 1
    float4 P2  = __ldg(pre4 + 2);  // P1 row 2
    float4 KC  = __ldg(pre4 + 3);  // fx0, cx0, fy0, cy0
    float p10[4] = {P0.x, P0.y, P0.z, P0.w};
    float p11[4] = {P1r.x, P1r.y, P1r.z, P1r.w};
    float p12[4] = {P2.x, P2.y, P2.z, P2.w};

    // ---- per-point data (coalesced vector loads) ----
    float2 pt0 = __ldg(((const float2*)kpts0) + i);
    float2 pt1 = __ldg(((const float2*)kpts1) + i);
    float m = __ldg(mconf + i);
    float x0 = pt0.x, y0 = pt0.y;
    float x1 = pt1.x, y1 = pt1.y;

    // ---- build B = A^T, stored as 4 COLUMNS b[col][row] (col j = A row j) ----
    // A row0 = [-fx, 0, x0-cx, 0]; A row1 = [0, -fy, y0-cy, 0]
    // A row2 = m*(x1*P1[2]-P1[0]); A row3 = m*(y1*P1[2]-P1[1])
    float b[4][4];
    b[0][0] = -KC.x; b[0][1] = 0.0f;       b[0][2] = x0 - KC.y; b[0][3] = 0.0f;
    b[1][0] = 0.0f;  b[1][1] = -KC.z;      b[1][2] = y0 - KC.w; b[1][3] = 0.0f;
#pragma unroll
    for (int j = 0; j < 4; j++) {
        b[2][j] = m * fmaf(x1, p12[j], -p10[j]);
        b[3][j] = m * fmaf(y1, p12[j], -p11[j]);
    }

    // ---- one-sided Jacobi on B's columns (= A's rows), 5 cyclic sweeps.
    // B = A^T = V*Sigma*U^T; orthogonalizing B's columns converges to
    // B_final = V*Sigma (up to signed permutation). The min-norm column of
    // B_final is sigma4 * v4, and the answer z = v4[2]/v4[3] is scale-free:
    // no V accumulation needed at all.
    const int PP[6] = {0, 0, 0, 1, 1, 2};
    const int QQ[6] = {1, 2, 3, 2, 3, 3};

#pragma unroll
    for (int sweep = 0; sweep < 5; sweep++) {
#pragma unroll
        for (int rr = 0; rr < 6; rr++) {
            const int p = PP[rr], q = QQ[rr];
            // exact Gram entries of the column pair (no maintained norms:
            // round-8 lesson — running-difference norms drift ~eps*sigma1^2
            // and corrupt the argmin/angles)
            float al = b[p][0] * b[p][0];
            float be = b[q][0] * b[q][0];
            float g  = b[p][0] * b[q][0];
#pragma unroll
            for (int k = 1; k < 4; k++) {
                al = fmaf(b[p][k], b[p][k], al);
                be = fmaf(b[q][k], b[q][k], be);
                g  = fmaf(b[p][k], b[q][k], g);
            }
            // relative convergence test: skip already-orthogonal pairs
            if (g * g > 1e-14f * al * be) {
                float d = be - al;
                float u = fmaf(d, d, 4.0f * g * g);
                float rsq = frsqrt(u);
                float cos2 = fabsf(d) * rsq;               // cos(2t)
                float sin2 = copysignf(1.0f, d) * (2.0f * g * rsq);
                float w = fmaf(0.5f, cos2, 0.5f);          // cos(t)^2
                float rw = frsqrt(w);
                float c = w * rw;                          // cos(t)
                float s = 0.5f * sin2 * rw;                // sin(t)
                // rotate columns p,q of B
#pragma unroll
                for (int k = 0; k < 4; k++) {
                    float bp = b[p][k], bq = b[q][k];
                    b[p][k] = fmaf(-s, bq, c * bp);
                    b[q][k] = fmaf(s, bp, c * bq);
                }
            }
        }
    }

    // ---- min-norm column = sigma4 * v4; ratio of rows 2,3 is the answer ----
    int jm = 0;
    float best = 3.4e38f;
#pragma unroll
    for (int j = 0; j < 4; j++) {
        float n2 = b[j][0] * b[j][0];
#pragma unroll
        for (int k = 1; k < 4; k++) n2 = fmaf(b[j][k], b[j][k], n2);
        if (n2 < best) { best = n2; jm = j; }
    }

    float z = __fdividef(b[jm][2], b[jm][3]);  // sigma4 and vector sign cancel

    // clip like reference: [-1000,1000] then [0,30], then band filter
    z = fminf(fmaxf(z, -1000.0f), 1000.0f);
    float z2 = fminf(fmaxf(z, 0.0f), 30.0f);
    float kp = (z2 > 0.0f && z2 < 30.0f) ? z2 : 0.0f;

    out[HW + i] = kp;

    // ---- last-write-wins scatter (highest point index wins, like serial .set) ----
    int xi = (int)x0;
    int yi = (int)y0;
    u64 packed = (((u64)(unsigned)(i + 1)) << 32) | (u64)__float_as_uint(kp);
    atomicMax(&g_scratch[yi * WW + xi], packed);
}

extern "C" void kernel_launch(void* const* d_in, const int* in_sizes, int n_in,
                              void* d_out, int out_size) {
    // metadata order: T_0to1, K0, K1, mconf, mkpts0_f, mkpts1_f, image0, m_bids
    const float* T     = (const float*)d_in[0];
    const float* K0    = (const float*)d_in[1];
    const float* K1    = (const float*)d_in[2];
    const float* mconf = (const float*)d_in[3];
    const float* kp0   = (const float*)d_in[4];
    const float* kp1   = (const float*)d_in[5];
    float* out = (float*)d_out;
    int n = in_sizes[3];  // mconf element count = N

    const int T1 = 256;
    setup_kernel<<<1, 32>>>(T, K0, K1);
    triangulate_kernel<<<(n + T1 - 1) / T1, T1>>>(mconf, kp0, kp1, out, n);
    finalize_depth_kernel<<<(HW + T1 - 1) / T1, T1>>>(out);
}

// round 11
// speedup vs baseline: 1.3317x; 1.1204x over previous
#include <cuda_runtime.h>
#include <cstdint>

// Fixed-shape problem: H=480, W=640, N=1e6
#define HH 480
#define WW 640
#define HW (HH * WW)

typedef unsigned long long u64;

// last-write-wins scatter scratch: (n+1)<<32 | float_bits(kp).
// Zero-initialized at module load; finalize_depth_kernel resets it to zero
// after every use, so every kernel_launch call (and graph replay) sees zeros.
__device__ u64 g_scratch[HW];

// Finalize: 4 pixels per thread (vectorized), and reset scratch to zero.
__global__ void finalize_depth_kernel(float* __restrict__ out) {
    int i = blockIdx.x * blockDim.x + threadIdx.x;   // pixel group id
    if (i < HW / 4) {
        ulonglong2* sc = (ulonglong2*)&g_scratch[i * 4];
        ulonglong2 p01 = sc[0];
        ulonglong2 p23 = sc[1];
        float4 v;
        v.x = __uint_as_float((unsigned)(p01.x & 0xffffffffULL));
        v.y = __uint_as_float((unsigned)(p01.y & 0xffffffffULL));
        v.z = __uint_as_float((unsigned)(p23.x & 0xffffffffULL));
        v.w = __uint_as_float((unsigned)(p23.y & 0xffffffffULL));
        *(float4*)(out + i * 4) = v;
        sc[0] = make_ulonglong2(0ULL, 0ULL);  // leave zeroed for next replay
        sc[1] = make_ulonglong2(0ULL, 0ULL);
    }
}

// MUFU.RSQ: 2 issue slots on the otherwise-idle MUFU pipe instead of 7 ops on
// the saturated FMA pipe. ~2e-7 rel err (better than the 2-NR bit trick).
__device__ __forceinline__ float rsqrt_approx(float x) {
    float y;
    asm("rsqrt.approx.f32 %0, %1;" : "=f"(y) : "f"(x));
    return y;
}

__global__ void __launch_bounds__(256) triangulate_kernel(
    const float* __restrict__ T,      // [4,4]
    const float* __restrict__ K0,     // [3,3]
    const float* __restrict__ K1,     // [3,3]
    const float* __restrict__ mconf,  // [N]
    const float* __restrict__ kpts0,  // [N,2]
    const float* __restrict__ kpts1,  // [N,2]
    float* __restrict__ out,          // [HW + N]
    int n)
{
    int i = blockIdx.x * blockDim.x + threadIdx.x;
    if (i >= n) return;

    // ---- camera constants, computed per-thread (L1-resident broadcast loads;
    // cheaper than a dedicated 4us setup-kernel launch) ----
    float fx0 = __ldg(K0 + 0), cx0 = __ldg(K0 + 2);
    float fy0 = __ldg(K0 + 4), cy0 = __ldg(K0 + 5);
    float p10[4], p11[4], p12[4];
#pragma unroll
    for (int c = 0; c < 4; c++) {
        float t0 = __ldg(T + 0 * 4 + c);
        float t1 = __ldg(T + 1 * 4 + c);
        float t2 = __ldg(T + 2 * 4 + c);
        p10[c] = __ldg(K1 + 0) * t0 + __ldg(K1 + 1) * t1 + __ldg(K1 + 2) * t2;
        p11[c] = __ldg(K1 + 3) * t0 + __ldg(K1 + 4) * t1 + __ldg(K1 + 5) * t2;
        p12[c] = __ldg(K1 + 6) * t0 + __ldg(K1 + 7) * t1 + __ldg(K1 + 8) * t2;
    }

    // ---- per-point data (coalesced vector loads) ----
    float2 pt0 = __ldg(((const float2*)kpts0) + i);
    float2 pt1 = __ldg(((const float2*)kpts1) + i);
    float m = __ldg(mconf + i);
    float x0 = pt0.x, y0 = pt0.y;
    float x1 = pt1.x, y1 = pt1.y;

    // ---- build B = A^T, stored as 4 COLUMNS b[col][row] (col j = A row j) ----
    // A row0 = [-fx, 0, x0-cx, 0]; A row1 = [0, -fy, y0-cy, 0]
    // A row2 = m*(x1*P1[2]-P1[0]); A row3 = m*(y1*P1[2]-P1[1])
    float b[4][4];
    b[0][0] = -fx0; b[0][1] = 0.0f; b[0][2] = x0 - cx0; b[0][3] = 0.0f;
    b[1][0] = 0.0f; b[1][1] = -fy0; b[1][2] = y0 - cy0; b[1][3] = 0.0f;
#pragma unroll
    for (int j = 0; j < 4; j++) {
        b[2][j] = m * fmaf(x1, p12[j], -p10[j]);
        b[3][j] = m * fmaf(y1, p12[j], -p11[j]);
    }

    // ---- one-sided Jacobi on B's columns (= A's rows), 5 cyclic sweeps.
    // B = A^T = V*Sigma*U^T; orthogonalizing B's columns converges to
    // B_final = V*Sigma. The min-norm column of B_final is sigma4*v4, and
    // z = v4[2]/v4[3] is scale-free: no V accumulation needed.
    const int PP[6] = {0, 0, 0, 1, 1, 2};
    const int QQ[6] = {1, 2, 3, 2, 3, 3};

#pragma unroll
    for (int sweep = 0; sweep < 5; sweep++) {
#pragma unroll
        for (int rr = 0; rr < 6; rr++) {
            const int p = PP[rr], q = QQ[rr];
            // exact Gram entries (round-8 lesson: no maintained norms)
            float al = b[p][0] * b[p][0];
            float be = b[q][0] * b[q][0];
            float g  = b[p][0] * b[q][0];
#pragma unroll
            for (int k = 1; k < 4; k++) {
                al = fmaf(b[p][k], b[p][k], al);
                be = fmaf(b[q][k], b[q][k], be);
                g  = fmaf(b[p][k], b[q][k], g);
            }
            // relative convergence test: skip already-orthogonal pairs
            if (g * g > 1e-14f * al * be) {
                float d = be - al;
                float u = fmaf(d, d, 4.0f * g * g);
                float rsq = rsqrt_approx(u);
                float cos2 = fabsf(d) * rsq;               // cos(2t)
                float sin2 = copysignf(1.0f, d) * (2.0f * g * rsq);
                float w = fmaf(0.5f, cos2, 0.5f);          // cos(t)^2
                float rw = rsqrt_approx(w);
                float c = w * rw;                          // cos(t)
                float s = 0.5f * sin2 * rw;                // sin(t)
                // rotate columns p,q of B
#pragma unroll
                for (int k = 0; k < 4; k++) {
                    float bp = b[p][k], bq = b[q][k];
                    b[p][k] = fmaf(-s, bq, c * bp);
                    b[q][k] = fmaf(s, bp, c * bq);
                }
            }
        }
    }

    // ---- min-norm column = sigma4 * v4; ratio of rows 2,3 is the answer ----
    int jm = 0;
    float best = 3.4e38f;
#pragma unroll
    for (int j = 0; j < 4; j++) {
        float n2 = b[j][0] * b[j][0];
#pragma unroll
        for (int k = 1; k < 4; k++) n2 = fmaf(b[j][k], b[j][k], n2);
        if (n2 < best) { best = n2; jm = j; }
    }

    float z = __fdividef(b[jm][2], b[jm][3]);  // sigma4 and vector sign cancel

    // clip like reference: [-1000,1000] then [0,30], then band filter
    z = fminf(fmaxf(z, -1000.0f), 1000.0f);
    float z2 = fminf(fmaxf(z, 0.0f), 30.0f);
    float kp = (z2 > 0.0f && z2 < 30.0f) ? z2 : 0.0f;

    out[HW + i] = kp;

    // ---- last-write-wins scatter (highest point index wins, like serial .set) ----
    int xi = (int)x0;
    int yi = (int)y0;
    u64 packed = (((u64)(unsigned)(i + 1)) << 32) | (u64)__float_as_uint(kp);
    atomicMax(&g_scratch[yi * WW + xi], packed);
}

extern "C" void kernel_launch(void* const* d_in, const int* in_sizes, int n_in,
                              void* d_out, int out_size) {
    // metadata order: T_0to1, K0, K1, mconf, mkpts0_f, mkpts1_f, image0, m_bids
    const float* T     = (const float*)d_in[0];
    const float* K0    = (const float*)d_in[1];
    const float* K1    = (const float*)d_in[2];
    const float* mconf = (const float*)d_in[3];
    const float* kp0   = (const float*)d_in[4];
    const float* kp1   = (const float*)d_in[5];
    float* out = (float*)d_out;
    int n = in_sizes[3];  // mconf element count = N

    const int T1 = 256;
    triangulate_kernel<<<(n + T1 - 1) / T1, T1>>>(T, K0, K1, mconf, kp0, kp1, out, n);
    finalize_depth_kernel<<<(HW / 4 + T1 - 1) / T1, T1>>>(out);
}

// round 12
// speedup vs baseline: 1.3771x; 1.0341x over previous
#include <cuda_runtime.h>
#include <cstdint>

// Fixed-shape problem: H=480, W=640, N=1e6
#define HH 480
#define WW 640
#define HW (HH * WW)

typedef unsigned long long u64;

// last-write-wins scatter scratch: (n+1)<<32 | float_bits(kp).
// Zero-initialized at module load; finalize_depth_kernel resets it to zero
// after every use, so every kernel_launch call (and graph replay) sees zeros.
__device__ u64 g_scratch[HW];

// Finalize: 2 pixels per thread (vector loads, double the threads of the 4-px
// variant — round-11 data: 1px/4.4us beat 4px/5.0us; this is the midpoint).
__global__ void finalize_depth_kernel(float* __restrict__ out) {
    int i = blockIdx.x * blockDim.x + threadIdx.x;   // pixel pair id
    if (i < HW / 2) {
        ulonglong2* sc = (ulonglong2*)&g_scratch[i * 2];
        ulonglong2 p01 = sc[0];
        float2 v;
        v.x = __uint_as_float((unsigned)(p01.x & 0xffffffffULL));
        v.y = __uint_as_float((unsigned)(p01.y & 0xffffffffULL));
        *(float2*)(out + i * 2) = v;
        sc[0] = make_ulonglong2(0ULL, 0ULL);  // leave zeroed for next replay
    }
}

// MUFU.RSQ: 2 issue slots on the otherwise-idle MUFU pipe instead of 7 ops on
// the saturated FMA pipe. ~2e-7 rel err (better than the 2-NR bit trick).
__device__ __forceinline__ float rsqrt_approx(float x) {
    float y;
    asm("rsqrt.approx.f32 %0, %1;" : "=f"(y) : "f"(x));
    return y;
}

__global__ void __launch_bounds__(256) triangulate_kernel(
    const float* __restrict__ T,      // [4,4]
    const float* __restrict__ K0,     // [3,3]
    const float* __restrict__ K1,     // [3,3]
    const float* __restrict__ mconf,  // [N]
    const float* __restrict__ kpts0,  // [N,2]
    const float* __restrict__ kpts1,  // [N,2]
    float* __restrict__ out,          // [HW + N]
    int n)
{
    int i = blockIdx.x * blockDim.x + threadIdx.x;
    if (i >= n) return;

    // ---- camera constants, computed per-thread (L1-resident broadcast loads;
    // cheaper than a dedicated setup-kernel launch: round-11 evidence) ----
    float fx0 = __ldg(K0 + 0), cx0 = __ldg(K0 + 2);
    float fy0 = __ldg(K0 + 4), cy0 = __ldg(K0 + 5);
    float p10[4], p11[4], p12[4];
#pragma unroll
    for (int c = 0; c < 4; c++) {
        float t0 = __ldg(T + 0 * 4 + c);
        float t1 = __ldg(T + 1 * 4 + c);
        float t2 = __ldg(T + 2 * 4 + c);
        p10[c] = __ldg(K1 + 0) * t0 + __ldg(K1 + 1) * t1 + __ldg(K1 + 2) * t2;
        p11[c] = __ldg(K1 + 3) * t0 + __ldg(K1 + 4) * t1 + __ldg(K1 + 5) * t2;
        p12[c] = __ldg(K1 + 6) * t0 + __ldg(K1 + 7) * t1 + __ldg(K1 + 8) * t2;
    }

    // ---- per-point data (coalesced vector loads) ----
    float2 pt0 = __ldg(((const float2*)kpts0) + i);
    float2 pt1 = __ldg(((const float2*)kpts1) + i);
    float m = __ldg(mconf + i);
    float x0 = pt0.x, y0 = pt0.y;
    float x1 = pt1.x, y1 = pt1.y;

    // ---- build B = A^T, stored as 4 COLUMNS b[col][row] (col j = A row j) ----
    // A row0 = [-fx, 0, x0-cx, 0]; A row1 = [0, -fy, y0-cy, 0]
    // A row2 = m*(x1*P1[2]-P1[0]); A row3 = m*(y1*P1[2]-P1[1])
    float b[4][4];
    b[0][0] = -fx0; b[0][1] = 0.0f; b[0][2] = x0 - cx0; b[0][3] = 0.0f;
    b[1][0] = 0.0f; b[1][1] = -fy0; b[1][2] = y0 - cy0; b[1][3] = 0.0f;
#pragma unroll
    for (int j = 0; j < 4; j++) {
        b[2][j] = m * fmaf(x1, p12[j], -p10[j]);
        b[3][j] = m * fmaf(y1, p12[j], -p11[j]);
    }

    // ---- one-sided Jacobi on B's columns (= A's rows), 4 cyclic sweeps.
    // B = A^T = V*Sigma*U^T; orthogonalizing B's columns converges to
    // B_final = V*Sigma. The min-norm column of B_final is sigma4*v4, and
    // z = v4[2]/v4[3] is scale-free: no V accumulation needed.
    // 4 sweeps (vs 5): now safe because rotations use MUFU.RSQ (~2e-7 angle
    // err) — round-6's 4-sweep failure was the sloppy 1-NR rsqrt, not sweeps.
    const int PP[6] = {0, 0, 0, 1, 1, 2};
    const int QQ[6] = {1, 2, 3, 2, 3, 3};

#pragma unroll
    for (int sweep = 0; sweep < 4; sweep++) {
#pragma unroll
        for (int rr = 0; rr < 6; rr++) {
            const int p = PP[rr], q = QQ[rr];
            // exact Gram entries (round-8 lesson: no maintained norms)
            float al = b[p][0] * b[p][0];
            float be = b[q][0] * b[q][0];
            float g  = b[p][0] * b[q][0];
#pragma unroll
            for (int k = 1; k < 4; k++) {
                al = fmaf(b[p][k], b[p][k], al);
                be = fmaf(b[q][k], b[q][k], be);
                g  = fmaf(b[p][k], b[q][k], g);
            }
            // relative convergence test: skip already-orthogonal pairs
            if (g * g > 1e-14f * al * be) {
                float d = be - al;
                float u = fmaf(d, d, 4.0f * g * g);
                float rsq = rsqrt_approx(u);
                float cos2 = fabsf(d) * rsq;               // cos(2t)
                float sin2 = copysignf(1.0f, d) * (2.0f * g * rsq);
                float w = fmaf(0.5f, cos2, 0.5f);          // cos(t)^2
                float rw = rsqrt_approx(w);
                float c = w * rw;                          // cos(t)
                float s = 0.5f * sin2 * rw;                // sin(t)
                // rotate columns p,q of B
#pragma unroll
                for (int k = 0; k < 4; k++) {
                    float bp = b[p][k], bq = b[q][k];
                    b[p][k] = fmaf(-s, bq, c * bp);
                    b[q][k] = fmaf(s, bp, c * bq);
                }
            }
        }
    }

    // ---- min-norm column = sigma4 * v4; ratio of rows 2,3 is the answer ----
    int jm = 0;
    float best = 3.4e38f;
#pragma unroll
    for (int j = 0; j < 4; j++) {
        float n2 = b[j][0] * b[j][0];
#pragma unroll
        for (int k = 1; k < 4; k++) n2 = fmaf(b[j][k], b[j][k], n2);
        if (n2 < best) { best = n2; jm = j; }
    }

    float z = __fdividef(b[jm][2], b[jm][3]);  // sigma4 and vector sign cancel

    // clip like reference: [-1000,1000] then [0,30], then band filter
    z = fminf(fmaxf(z, -1000.0f), 1000.0f);
    float z2 = fminf(fmaxf(z, 0.0f), 30.0f);
    float kp = (z2 > 0.0f && z2 < 30.0f) ? z2 : 0.0f;

    out[HW + i] = kp;

    // ---- last-write-wins scatter (highest point index wins, like serial .set) ----
    int xi = (int)x0;
    int yi = (int)y0;
    u64 packed = (((u64)(unsigned)(i + 1)) << 32) | (u64)__float_as_uint(kp);
    atomicMax(&g_scratch[yi * WW + xi], packed);
}

extern "C" void kernel_launch(void* const* d_in, const int* in_sizes, int n_in,
                              void* d_out, int out_size) {
    // metadata order: T_0to1, K0, K1, mconf, mkpts0_f, mkpts1_f, image0, m_bids
    const float* T     = (const float*)d_in[0];
    const float* K0    = (const float*)d_in[1];
    const float* K1    = (const float*)d_in[2];
    const float* mconf = (const float*)d_in[3];
    const float* kp0   = (const float*)d_in[4];
    const float* kp1   = (const float*)d_in[5];
    float* out = (float*)d_out;
    int n = in_sizes[3];  // mconf element count = N

    const int T1 = 256;
    triangulate_kernel<<<(n + T1 - 1) / T1, T1>>>(T, K0, K1, mconf, kp0, kp1, out, n);
    finalize_depth_kernel<<<(HW / 2 + T1 - 1) / T1, T1>>>(out);
}

// round 14
// speedup vs baseline: 1.6861x; 1.2244x over previous
#include <cuda_runtime.h>
#include <cstdint>

// Fixed-shape problem: H=480, W=640, N=1e6
#define HH 480
#define WW 640
#define HW (HH * WW)

typedef unsigned long long u64;

// last-write-wins scatter scratch: (n+1)<<32 | float_bits(kp).
// Zero-initialized at module load; finalize_depth_kernel resets it to zero
// after every use, so every kernel_launch call (and graph replay) sees zeros.
__device__ u64 g_scratch[HW];

// Finalize: 1 pixel/thread — measured fastest config (4.38us, round 7/11 data).
__global__ void finalize_depth_kernel(float* __restrict__ out) {
    int i = blockIdx.x * blockDim.x + threadIdx.x;
    if (i < HW) {
        u64 p = g_scratch[i];
        out[i] = __uint_as_float((unsigned)(p & 0xffffffffULL));
        g_scratch[i] = 0ULL;  // leave zeroed for next replay
    }
}

// MUFU.RSQ: rt 8 on the idle MUFU pipe; its 48 ops/pt cost ~10us of pipe time,
// fully hidden under ~35us of fma-pipe work. ~2e-7 rel err.
__device__ __forceinline__ float rsqrt_approx(float x) {
    float y;
    asm("rsqrt.approx.f32 %0, %1;" : "=f"(y) : "f"(x));
    return y;
}

// flip sign of x when d < 0, preserving x's own sign (LOP3 on ALU pipe;
// NOT copysignf — that would discard sign(x): the round-2 bug).
__device__ __forceinline__ float sign_flip_if_neg(float x, float d) {
    return __uint_as_float(__float_as_uint(x) ^
                           (__float_as_uint(d) & 0x80000000u));
}

__global__ void __launch_bounds__(256) triangulate_kernel(
    const float* __restrict__ T,      // [4,4]
    const float* __restrict__ K0,     // [3,3]
    const float* __restrict__ K1,     // [3,3]
    const float* __restrict__ mconf,  // [N]
    const float* __restrict__ kpts0,  // [N,2]
    const float* __restrict__ kpts1,  // [N,2]
    float* __restrict__ out,          // [HW + N]
    int n)
{
    int i = blockIdx.x * blockDim.x + threadIdx.x;
    if (i >= n) return;

    // ---- camera constants (L1-resident broadcast loads). Both K are
    // intrinsic matrices [fx 0 cx; 0 fy cy; 0 0 1] — structure already
    // load-bearing for the K0 rows; exploit it for K1 too: P1 never
    // materializes. ----
    float fx0 = __ldg(K0 + 0), cx0 = __ldg(K0 + 2);
    float fy0 = __ldg(K0 + 4), cy0 = __ldg(K0 + 5);
    float fx1 = __ldg(K1 + 0), cx1 = __ldg(K1 + 2);
    float fy1 = __ldg(K1 + 4), cy1 = __ldg(K1 + 5);
    float4 T0 = __ldg((const float4*)T + 0);  // T row 0
    float4 T1 = __ldg((const float4*)T + 1);  // T row 1
    float4 T2 = __ldg((const float4*)T + 2);  // T row 2
    float t0[4] = {T0.x, T0.y, T0.z, T0.w};
    float t1[4] = {T1.x, T1.y, T1.z, T1.w};
    float t2[4] = {T2.x, T2.y, T2.z, T2.w};

    // ---- per-point data (coalesced vector loads) ----
    float2 pt0 = __ldg(((const float2*)kpts0) + i);
    float2 pt1 = __ldg(((const float2*)kpts1) + i);
    float m = __ldg(mconf + i);
    float x0 = pt0.x, y0 = pt0.y;
    float x1 = pt1.x, y1 = pt1.y;

    // ---- build B = A^T, stored as 4 COLUMNS b[col][row] (col j = A row j).
    // A row2 = m*(x1*P1[2]-P1[0]) = m*(x1-cx1)*T2 - m*fx1*T0  (K1 intrinsic)
    // A row3 = m*(y1-cy1)*T2 - m*fy1*T1
    float mfx = m * fx1, mfy = m * fy1;
    float mx = m * (x1 - cx1), my = m * (y1 - cy1);
    float u2 = x0 - cx0, w2 = y0 - cy0;
    float b[4][4];
    b[0][0] = -fx0; b[0][1] = 0.0f; b[0][2] = u2; b[0][3] = 0.0f;
    b[1][0] = 0.0f; b[1][1] = -fy0; b[1][2] = w2; b[1][3] = 0.0f;
#pragma unroll
    for (int j = 0; j < 4; j++) {
        b[2][j] = fmaf(mx, t2[j], -(mfx * t0[j]));
        b[3][j] = fmaf(my, t2[j], -(mfy * t1[j]));
    }

    // ---- initial column norms (exploit structural zeros; exact) ----
    float nrm[4];
    nrm[0] = fmaf(fx0, fx0, u2 * u2);
    nrm[1] = fmaf(fy0, fy0, w2 * w2);
    nrm[2] = fmaf(b[2][0], b[2][0], fmaf(b[2][1], b[2][1],
              fmaf(b[2][2], b[2][2], b[2][3] * b[2][3])));
    nrm[3] = fmaf(b[3][0], b[3][0], fmaf(b[3][1], b[3][1],
              fmaf(b[3][2], b[3][2], b[3][3] * b[3][3])));

    // ---- one-sided Jacobi on B's columns (= A's rows), 4 cyclic sweeps.
    // B = A^T = V*Sigma*U^T; min-norm column of B_final = sigma4*v4 and
    // z = v4[2]/v4[3] is scale-free (no V accumulation).
    // Norms: maintained within a sweep (Rutishauser), refreshed EXACTLY at
    // each sweep start and for the final argmin — bounds drift to <=3
    // rotations (round-8's all-sweeps drift corrupted argmin; this doesn't).
    const int PP[6] = {0, 0, 0, 1, 1, 2};
    const int QQ[6] = {1, 2, 3, 2, 3, 3};

#pragma unroll
    for (int sweep = 0; sweep < 4; sweep++) {
        if (sweep > 0) {
            // exact norm refresh
#pragma unroll
            for (int j = 0; j < 4; j++) {
                float n2 = b[j][0] * b[j][0];
#pragma unroll
                for (int k = 1; k < 4; k++) n2 = fmaf(b[j][k], b[j][k], n2);
                nrm[j] = n2;
            }
        }
#pragma unroll
        for (int rr = 0; rr < 6; rr++) {
            const int p = PP[rr], q = QQ[rr];
            float g = b[p][0] * b[q][0];
#pragma unroll
            for (int k = 1; k < 4; k++) g = fmaf(b[p][k], b[q][k], g);
            float al = nrm[p], be = nrm[q];
            // sweeps 1-2: rotations always fire — skip the test overhead.
            // sweeps 3-4: relative convergence test skips orthogonal pairs.
            bool doit = (sweep < 2) || (g * g > 1e-14f * al * be);
            if (doit) {
                float d = be - al;
                float g2 = g + g;
                float u = fmaf(g2, g2, fmaf(d, d, 1e-29f));  // keep u > 0
                float rsq = rsqrt_approx(u);
                float cos2 = fabsf(d) * rsq;           // cos(2t)
                float w = fmaf(0.5f, cos2, 0.5f);      // cos(t)^2
                float rw = rsqrt_approx(w);            // 1/cos(t)
                float c = w * rw;                      // cos(t)
                float S = g * rsq;                     // sin(2t)/2 * sign(g-part)
                float s = sign_flip_if_neg(S * rw, d); // sin(t), keeps sign of g AND d
                // Rutishauser within-sweep norm update: exact refresh next sweep
                float hg = (s * rw) * g;               // tan(t)*g
                nrm[p] = al - hg;
                nrm[q] = be + hg;
                // rotate columns p,q of B
#pragma unroll
                for (int k = 0; k < 4; k++) {
                    float bp = b[p][k], bq = b[q][k];
                    b[p][k] = fmaf(-s, bq, c * bp);
                    b[q][k] = fmaf(s, bp, c * bq);
                }
            }
        }
    }

    // ---- final argmin over EXACT norms (never the maintained ones) ----
    int jm = 0;
    float best = 3.4e38f;
#pragma unroll
    for (int j = 0; j < 4; j++) {
        float n2 = b[j][0] * b[j][0];
#pragma unroll
        for (int k = 1; k < 4; k++) n2 = fmaf(b[j][k], b[j][k], n2);
        if (n2 < best) { best = n2; jm = j; }
    }

    float z = __fdividef(b[jm][2], b[jm][3]);  // sigma4 and vector sign cancel

    // clip like reference: [-1000,1000] then [0,30], then band filter
    z = fminf(fmaxf(z, -1000.0f), 1000.0f);
    float z2 = fminf(fmaxf(z, 0.0f), 30.0f);
    float kp = (z2 > 0.0f && z2 < 30.0f) ? z2 : 0.0f;

    out[HW + i] = kp;

    // ---- last-write-wins scatter (highest point index wins, like serial .set) ----
    int xi = (int)x0;
    int yi = (int)y0;
    u64 packed = (((u64)(unsigned)(i + 1)) << 32) | (u64)__float_as_uint(kp);
    atomicMax(&g_scratch[yi * WW + xi], packed);
}

extern "C" void kernel_launch(void* const* d_in, const int* in_sizes, int n_in,
                              void* d_out, int out_size) {
    // metadata order: T_0to1, K0, K1, mconf, mkpts0_f, mkpts1_f, image0, m_bids
    const float* T     = (const float*)d_in[0];
    const float* K0    = (const float*)d_in[1];
    const float* K1    = (const float*)d_in[2];
    const float* mconf = (const float*)d_in[3];
    const float* kp0   = (const float*)d_in[4];
    const float* kp1   = (const float*)d_in[5];
    float* out = (float*)d_out;
    int n = in_sizes[3];  // mconf element count = N

    const int T1 = 256;
    triangulate_kernel<<<(n + T1 - 1) / T1, T1>>>(T, K0, K1, mconf, kp0, kp1, out, n);
    finalize_depth_kernel<<<(HW + T1 - 1) / T1, T1>>>(out);
}